// round 7
// baseline (speedup 1.0000x reference)
#include <cuda_runtime.h>
#include <cuda_bf16.h>
#include <cstdint>

#define F_IN  512
#define HID   16
#define C_OUT 40
#define MAXN  100000
#define MAXE  3200000

typedef unsigned long long ull;
typedef unsigned int u32;

// ---------------- scratch (static device globals, no allocs) ----------------
__device__ __align__(128) int   g_deg [MAXN];
__device__ __align__(128) float g_dinv[MAXN];
__device__ __align__(128) float g_B1  [MAXN * HID];   // h~, later a~ (agg gather input)
__device__ __align__(128) float g_B2  [MAXN * HID];   // agg accumulators

// ---------------- helpers ----------------
__device__ __forceinline__ void red4(float* p, float a, float b, float c, float d) {
    asm volatile("red.global.add.v4.f32 [%0], {%1,%2,%3,%4};"
                 :: "l"(p), "f"(a), "f"(b), "f"(c), "f"(d) : "memory");
}
__device__ __forceinline__ ull pkdup(float v) {
    ull r;
    asm("mov.b64 %0, {%1, %1};" : "=l"(r) : "f"(v));
    return r;
}
__device__ __forceinline__ float2 upk2(ull v) {
    float2 f;
    asm("mov.b64 {%0, %1}, %2;" : "=f"(f.x), "=f"(f.y) : "l"(v));
    return f;
}
__device__ __forceinline__ void fma2(ull& d, ull a, ull b) {
    asm("fma.rn.f32x2 %0, %1, %2, %0;" : "+l"(d) : "l"(a), "l"(b));
}
__device__ __forceinline__ u32 s2u(const void* p) {
    u32 a;
    asm("{ .reg .u64 t; cvta.to.shared.u64 t, %1; cvt.u32.u64 %0, t; }"
        : "=r"(a) : "l"(p));
    return a;
}
__device__ __forceinline__ void cpa16(u32 dst, const void* src, int sz) {
    asm volatile("cp.async.cg.shared.global [%0], [%1], 16, %2;"
                 :: "r"(dst), "l"(src), "r"(sz) : "memory");
}
__device__ __forceinline__ void cpa_commit() {
    asm volatile("cp.async.commit_group;" ::: "memory");
}
template <int NN>
__device__ __forceinline__ void cpa_wait() {
    asm volatile("cp.async.wait_group %0;" :: "n"(NN) : "memory");
}

// ---------------- small kernels ----------------
__global__ void k_zero(int* a, int N) {
    int i = blockIdx.x * blockDim.x + threadIdx.x;
    if (i < N) a[i] = 0;
}
__global__ void k_hist(const int* __restrict__ dst, int* deg, int E) {
    int i = blockIdx.x * blockDim.x + threadIdx.x;
    if (i < E) atomicAdd(&deg[dst[i]], 1);
}
__global__ void k_dinv(const int* __restrict__ deg, float* dinv, int N) {
    int i = blockIdx.x * blockDim.x + threadIdx.x;
    if (i < N) dinv[i] = rsqrtf((float)(deg[i] + 1));
}

// ---------------- GEMM1 v4: cp.async double-buffered, full K, dual store -----
// 256 threads, 256 rows/block, 1 row/thread. x tile 256x16 staged per kt.
#define G1_RS 20   // floats per smem row (16 data + 4 pad): conflict-free LDS.128
__global__ __launch_bounds__(256) void k_gemm1(const float* __restrict__ x,
                                               const float* __restrict__ W1,
                                               const float* __restrict__ dinv,
                                               float* __restrict__ h0,
                                               float* __restrict__ h1, int N) {
    __shared__ __align__(16) float sx[2][256 * G1_RS];   // 2 x 20KB
    __shared__ __align__(16) ull   wt[2][128];           // 2 x 1KB
    const int t    = threadIdx.x;
    const int base = blockIdx.x * 256;
    const int row  = base + t;

    // per-thread staging coords: 4 chunks, chunk j covers (r_j, q_j)
    int rr[4], qq[4];
    u32 sx_dst[2][4];
    const float* srcb[4];
    int ssz[4];
#pragma unroll
    for (int j = 0; j < 4; j++) {
        int idx = t + 256 * j;
        rr[j] = idx >> 2;
        qq[j] = idx & 3;
        sx_dst[0][j] = s2u(&sx[0][rr[j] * G1_RS + qq[j] * 4]);
        sx_dst[1][j] = s2u(&sx[1][rr[j] * G1_RS + qq[j] * 4]);
        srcb[j] = x + (size_t)(base + rr[j]) * F_IN + qq[j] * 4;
        ssz[j] = (base + rr[j] < N) ? 16 : 0;
    }
    u32 wt_dst[2];
    wt_dst[0] = s2u(&wt[0][0]) + (t & 63) * 16;
    wt_dst[1] = s2u(&wt[1][0]) + (t & 63) * 16;

    ull acc[8];
#pragma unroll
    for (int j = 0; j < 8; j++) acc[j] = 0ull;

    // stage kt=0 into buf 0
    {
        if (t < 64) cpa16(wt_dst[0], W1 + t * 4, 16);
#pragma unroll
        for (int j = 0; j < 4; j++) cpa16(sx_dst[0][j], srcb[j], ssz[j]);
        cpa_commit();
    }

    for (int kt = 0; kt < 32; kt++) {
        const int buf = kt & 1;
        if (kt < 31) {
            const int nb = buf ^ 1;
            const int kg = (kt + 1) * 16;
            if (t < 64) cpa16(wt_dst[nb], W1 + (kt + 1) * 256 + t * 4, 16);
#pragma unroll
            for (int j = 0; j < 4; j++) cpa16(sx_dst[nb][j], srcb[j] + kg, ssz[j]);
            cpa_commit();
            cpa_wait<1>();
        } else {
            cpa_wait<0>();
        }
        __syncthreads();

        // load this thread's 16 k-values (4 conflict-free LDS.128)
        float4 xr[4];
#pragma unroll
        for (int q = 0; q < 4; q++)
            xr[q] = *(const float4*)&sx[buf][t * G1_RS + q * 4];
#pragma unroll
        for (int g = 0; g < 4; g++) {
#pragma unroll
            for (int e = 0; e < 4; e++) {
                const int kk = 4 * g + e;
                float s = (e == 0) ? xr[g].x : (e == 1) ? xr[g].y
                        : (e == 2) ? xr[g].z : xr[g].w;
                ull xs = pkdup(s);
                const ulonglong2* w2 = (const ulonglong2*)&wt[buf][kk * 8];
                ulonglong2 wa = w2[0], wb = w2[1], wc = w2[2], wd = w2[3];
                fma2(acc[0], xs, wa.x); fma2(acc[1], xs, wa.y);
                fma2(acc[2], xs, wb.x); fma2(acc[3], xs, wb.y);
                fma2(acc[4], xs, wc.x); fma2(acc[5], xs, wc.y);
                fma2(acc[6], xs, wd.x); fma2(acc[7], xs, wd.y);
            }
        }
        __syncthreads();
    }

    if (row < N) {
        float dv = dinv[row];
#pragma unroll
        for (int j4 = 0; j4 < 4; j4++) {
            float2 f0 = upk2(acc[2 * j4 + 0]);
            float2 f1 = upk2(acc[2 * j4 + 1]);
            float4 v = make_float4(f0.x * dv, f0.y * dv, f1.x * dv, f1.y * dv);
            *(float4*)&h0[(size_t)row * HID + 4 * j4] = v;
            *(float4*)&h1[(size_t)row * HID + 4 * j4] = v;
        }
    }
}

// ---------------- edge aggregation: out[dst] += in[src], 4 thr/edge ----------
__global__ void k_agg(const int* __restrict__ src, const int* __restrict__ dst,
                      const float4* __restrict__ in4, float* out, int E) {
    int tid = blockIdx.x * blockDim.x + threadIdx.x;
    int e = tid >> 2;
    int c = tid & 3;
    if (e < E) {
        int s = src[e];
        int d = dst[e];
        float4 v = __ldg(&in4[(size_t)s * 4 + c]);
        red4(&out[((size_t)d * 4 + c) * 4], v.x, v.y, v.z, v.w);
    }
}

// ---------------- a~ = dinv * relu(dinv * y1 + b1), dual store --------------
__global__ void k_relubias(const float4* __restrict__ in4, const float* __restrict__ dinv,
                           const float* __restrict__ b1,
                           float4* __restrict__ o0, float4* __restrict__ o1, int N) {
    int i = blockIdx.x * blockDim.x + threadIdx.x;
    if (i < N * (HID / 4)) {
        float dv = dinv[i >> 2];
        int jb = (i & 3) * 4;
        float4 v = in4[i];
        v.x = fmaxf(fmaf(v.x, dv, b1[jb + 0]), 0.f) * dv;
        v.y = fmaxf(fmaf(v.y, dv, b1[jb + 1]), 0.f) * dv;
        v.z = fmaxf(fmaf(v.z, dv, b1[jb + 2]), 0.f) * dv;
        v.w = fmaxf(fmaf(v.w, dv, b1[jb + 3]), 0.f) * dv;
        o0[i] = v;
        o1[i] = v;
    }
}

// ---------------- GEMM2 + b2 ----------------
__global__ __launch_bounds__(128) void k_gemm2(const float* __restrict__ y2,
                                               const float* __restrict__ dinv,
                                               const float* __restrict__ W2,
                                               const float* __restrict__ b2,
                                               float* __restrict__ out, int N) {
    __shared__ float w2s[HID * C_OUT];
    __shared__ float b2s[C_OUT];
    int t = threadIdx.x;
    for (int i = t; i < HID * C_OUT; i += 128) w2s[i] = W2[i];
    if (t < C_OUT) b2s[t] = b2[t];
    __syncthreads();
    int i = blockIdx.x * 128 + t;
    if (i >= N) return;
    float dv = dinv[i];
    float a[HID];
#pragma unroll
    for (int k4 = 0; k4 < 4; k4++) {
        float4 v = *(const float4*)&y2[(size_t)i * HID + 4 * k4];
        a[4 * k4 + 0] = v.x * dv; a[4 * k4 + 1] = v.y * dv;
        a[4 * k4 + 2] = v.z * dv; a[4 * k4 + 3] = v.w * dv;
    }
    float o[C_OUT];
#pragma unroll
    for (int j = 0; j < C_OUT; j++) o[j] = b2s[j];
#pragma unroll
    for (int k = 0; k < HID; k++) {
        float av = a[k];
#pragma unroll
        for (int j = 0; j < C_OUT; j++) o[j] += av * w2s[k * C_OUT + j];
    }
#pragma unroll
    for (int jg = 0; jg < C_OUT / 4; jg++) {
        float4 v = make_float4(o[4 * jg + 0], o[4 * jg + 1], o[4 * jg + 2], o[4 * jg + 3]);
        *(float4*)&out[(size_t)i * C_OUT + 4 * jg] = v;
    }
}

// ---------------- launcher ----------------
extern "C" void kernel_launch(void* const* d_in, const int* in_sizes, int n_in,
                              void* d_out, int out_size) {
    const float* x  = (const float*)d_in[0];
    const int*   ei = (const int*)d_in[1];
    const float* W1 = (const float*)d_in[2];
    const float* b1 = (const float*)d_in[3];
    const float* W2 = (const float*)d_in[4];
    const float* b2 = (const float*)d_in[5];
    float* out = (float*)d_out;

    const int N = in_sizes[0] / F_IN;
    const int E = in_sizes[1] / 2;
    const int* src = ei;
    const int* dst = ei + E;

    void *p;
    cudaGetSymbolAddress(&p, g_deg);  int*   deg  = (int*)p;
    cudaGetSymbolAddress(&p, g_dinv); float* dinv = (float*)p;
    cudaGetSymbolAddress(&p, g_B1);   float* B1   = (float*)p;
    cudaGetSymbolAddress(&p, g_B2);   float* B2   = (float*)p;

    const int TB = 256;
    const int nv4 = N * (HID / 4);

    // launch 0-2: degree + dinv
    k_zero<<<(N + TB - 1) / TB, TB>>>(deg, N);
    k_hist<<<(E + TB - 1) / TB, TB>>>(dst, deg, E);
    k_dinv<<<(N + TB - 1) / TB, TB>>>(deg, dinv, N);
    // launch 3 (profiled): h~ = dinv * (x @ W1) -> B1 and B2 (self-loop init)
    k_gemm1<<<(N + 255) / 256, 256>>>(x, W1, dinv, B1, B2, N);
    // launch 4: B2 += A * B1
    {
        int threads = E * 4;
        k_agg<<<(threads + TB - 1) / TB, TB>>>(src, dst, (const float4*)B1, B2, E);
    }
    // launch 5: a~ -> B1 and B2
    k_relubias<<<(nv4 + TB - 1) / TB, TB>>>((const float4*)B2, dinv, b1,
                                            (float4*)B1, (float4*)B2, N);
    // launch 6: B2 += A * B1
    {
        int threads = E * 4;
        k_agg<<<(threads + TB - 1) / TB, TB>>>(src, dst, (const float4*)B1, B2, E);
    }
    // launch 7: out = (dinv * B2) @ W2 + b2
    k_gemm2<<<(N + 127) / 128, 128>>>(B2, dinv, W2, b2, out, N);
}

// round 8
// speedup vs baseline: 1.0080x; 1.0080x over previous
#include <cuda_runtime.h>
#include <cuda_bf16.h>
#include <cstdint>

#define F_IN  512
#define HID   16
#define C_OUT 40
#define MAXN  100000
#define MAXE  3200000

typedef unsigned long long ull;
typedef unsigned int u32;

// ---------------- scratch (static device globals, no allocs) ----------------
__device__ __align__(128) int   g_deg [MAXN];
__device__ __align__(128) float g_dinv[MAXN];
__device__ __align__(128) float g_B1  [MAXN * HID];   // h~, later a~ (agg gather input)
__device__ __align__(128) float g_B2  [MAXN * HID];   // agg accumulators

// ---------------- helpers ----------------
__device__ __forceinline__ void red4(float* p, float a, float b, float c, float d) {
    asm volatile("red.global.add.v4.f32 [%0], {%1,%2,%3,%4};"
                 :: "l"(p), "f"(a), "f"(b), "f"(c), "f"(d) : "memory");
}
__device__ __forceinline__ ull pkdup(float v) {
    ull r;
    asm("mov.b64 %0, {%1, %1};" : "=l"(r) : "f"(v));
    return r;
}
__device__ __forceinline__ float2 upk2(ull v) {
    float2 f;
    asm("mov.b64 {%0, %1}, %2;" : "=f"(f.x), "=f"(f.y) : "l"(v));
    return f;
}
__device__ __forceinline__ void fma2(ull& d, ull a, ull b) {
    asm("fma.rn.f32x2 %0, %1, %2, %0;" : "+l"(d) : "l"(a), "l"(b));
}
__device__ __forceinline__ u32 s2u(const void* p) {
    u32 a;
    asm("{ .reg .u64 t; cvta.to.shared.u64 t, %1; cvt.u32.u64 %0, t; }"
        : "=r"(a) : "l"(p));
    return a;
}
__device__ __forceinline__ void cpa16(u32 dst, const void* src, int sz) {
    asm volatile("cp.async.cg.shared.global [%0], [%1], 16, %2;"
                 :: "r"(dst), "l"(src), "r"(sz) : "memory");
}
__device__ __forceinline__ void cpa_commit() {
    asm volatile("cp.async.commit_group;" ::: "memory");
}
template <int NN>
__device__ __forceinline__ void cpa_wait() {
    asm volatile("cp.async.wait_group %0;" :: "n"(NN) : "memory");
}

// ---------------- fused zero: deg + B1 + B2 ----------------
__global__ void k_zero_all(int* deg, float4* b1, float4* b2, int N, int nv4) {
    int i = blockIdx.x * blockDim.x + threadIdx.x;
    if (i < N) deg[i] = 0;
    if (i < nv4) {
        b1[i] = make_float4(0.f, 0.f, 0.f, 0.f);
        b2[i] = make_float4(0.f, 0.f, 0.f, 0.f);
    }
}
__global__ void k_hist(const int* __restrict__ dst, int* deg, int E) {
    int i = blockIdx.x * blockDim.x + threadIdx.x;
    if (i < E) atomicAdd(&deg[dst[i]], 1);
}
__global__ void k_dinv(const int* __restrict__ deg, float* dinv, int N) {
    int i = blockIdx.x * blockDim.x + threadIdx.x;
    if (i < N) dinv[i] = rsqrtf((float)(deg[i] + 1));
}

// ------- GEMM1 v5: 4 rows/thread + cp.async double-buffer, K-split 2 --------
// 128 threads, 512 rows/block, stages of 8 k. x stage stride 12 floats
// (8 data + 4 pad -> conflict-free LDS.128 phases).
#define G1_ST   12
#define G1_XSZ  (512 * G1_ST)        // floats per x stage buffer
__global__ __launch_bounds__(128) void k_gemm1(const float* __restrict__ x,
                                               const float* __restrict__ W1,
                                               const float* __restrict__ dinv,
                                               float* __restrict__ h0,
                                               float* __restrict__ h1, int N) {
    __shared__ __align__(16) float sx[2 * G1_XSZ];   // 2 x 24KB
    __shared__ __align__(16) ull   wt[2 * 64];       // 2 x 512B (8 kk x 16 cols)
    const int t    = threadIdx.x;
    const int base = blockIdx.x * 512;
    const int k0   = blockIdx.y * 256;

    // staging coords: 8 chunks/thread; chunk j -> row r, half q
    u32 sxd0[8];
    const float* sb[8];
    int  ssz[8];
#pragma unroll
    for (int j = 0; j < 8; j++) {
        int idx = t + 128 * j;
        int r = idx >> 1, q = idx & 1;
        sxd0[j] = s2u(&sx[r * G1_ST + q * 4]);
        sb[j]  = x + (size_t)(base + r) * F_IN + k0 + q * 4;
        ssz[j] = (base + r < N) ? 16 : 0;
    }
    const u32 wtd0  = s2u(&wt[0]) + (t & 31) * 16;
    const u32 XOFF  = G1_XSZ * 4;    // bytes between x buffers
    const u32 WOFF  = 64 * 8;        // bytes between w buffers

    ull acc[4][8];
#pragma unroll
    for (int m = 0; m < 4; m++)
#pragma unroll
        for (int j = 0; j < 8; j++) acc[m][j] = 0ull;

    // stage 0 into buf 0
    if (t < 32) cpa16(wtd0, W1 + (size_t)k0 * 16 + (t & 31) * 4, 16);
#pragma unroll
    for (int j = 0; j < 8; j++) cpa16(sxd0[j], sb[j], ssz[j]);
    cpa_commit();

    for (int kt = 0; kt < 32; kt++) {
        const int buf = kt & 1;
        if (kt < 31) {
            const int nb = buf ^ 1;
            const int kg = (kt + 1) * 8;
            if (t < 32) cpa16(wtd0 + nb * WOFF,
                              W1 + (size_t)(k0 + kg) * 16 + (t & 31) * 4, 16);
#pragma unroll
            for (int j = 0; j < 8; j++)
                cpa16(sxd0[j] + nb * XOFF, sb[j] + kg, ssz[j]);
            cpa_commit();
            cpa_wait<1>();
        } else {
            cpa_wait<0>();
        }
        __syncthreads();

        const float* sxb = &sx[buf * G1_XSZ];
        const ull*   wtb = &wt[buf * 64];
        float4 xr[4][2];
#pragma unroll
        for (int m = 0; m < 4; m++) {
            xr[m][0] = *(const float4*)&sxb[(t + 128 * m) * G1_ST];
            xr[m][1] = *(const float4*)&sxb[(t + 128 * m) * G1_ST + 4];
        }
#pragma unroll
        for (int kk = 0; kk < 8; kk++) {
            const ulonglong2* wp = (const ulonglong2*)&wtb[kk * 8];
            ulonglong2 wa = wp[0], wb = wp[1], wc = wp[2], wd = wp[3];
#pragma unroll
            for (int m = 0; m < 4; m++) {
                const float4& h = xr[m][kk >> 2];
                const int e = kk & 3;
                float s = (e == 0) ? h.x : (e == 1) ? h.y : (e == 2) ? h.z : h.w;
                ull xs = pkdup(s);
                fma2(acc[m][0], xs, wa.x); fma2(acc[m][1], xs, wa.y);
                fma2(acc[m][2], xs, wb.x); fma2(acc[m][3], xs, wb.y);
                fma2(acc[m][4], xs, wc.x); fma2(acc[m][5], xs, wc.y);
                fma2(acc[m][6], xs, wd.x); fma2(acc[m][7], xs, wd.y);
            }
        }
        __syncthreads();
    }

    // epilogue: scale K-partial by dinv (linear) and red into both buffers
#pragma unroll
    for (int m = 0; m < 4; m++) {
        int rg = base + t + 128 * m;
        if (rg < N) {
            float dv = dinv[rg];
#pragma unroll
            for (int j4 = 0; j4 < 4; j4++) {
                float2 f0 = upk2(acc[m][2 * j4 + 0]);
                float2 f1 = upk2(acc[m][2 * j4 + 1]);
                float a = f0.x * dv, b = f0.y * dv, c = f1.x * dv, d = f1.y * dv;
                red4(&h0[(size_t)rg * HID + 4 * j4], a, b, c, d);
                red4(&h1[(size_t)rg * HID + 4 * j4], a, b, c, d);
            }
        }
    }
}

// ---------------- edge aggregation: out[dst] += in[src], 4 thr/edge ----------
__global__ void k_agg(const int* __restrict__ src, const int* __restrict__ dst,
                      const float4* __restrict__ in4, float* out, int E) {
    int tid = blockIdx.x * blockDim.x + threadIdx.x;
    int e = tid >> 2;
    int c = tid & 3;
    if (e < E) {
        int s = src[e];
        int d = dst[e];
        float4 v = __ldg(&in4[(size_t)s * 4 + c]);
        red4(&out[((size_t)d * 4 + c) * 4], v.x, v.y, v.z, v.w);
    }
}

// ---------------- a~ = dinv * relu(dinv * y1 + b1), dual store --------------
__global__ void k_relubias(const float4* __restrict__ in4, const float* __restrict__ dinv,
                           const float* __restrict__ b1,
                           float4* __restrict__ o0, float4* __restrict__ o1, int N) {
    int i = blockIdx.x * blockDim.x + threadIdx.x;
    if (i < N * (HID / 4)) {
        float dv = dinv[i >> 2];
        int jb = (i & 3) * 4;
        float4 v = in4[i];
        v.x = fmaxf(fmaf(v.x, dv, b1[jb + 0]), 0.f) * dv;
        v.y = fmaxf(fmaf(v.y, dv, b1[jb + 1]), 0.f) * dv;
        v.z = fmaxf(fmaf(v.z, dv, b1[jb + 2]), 0.f) * dv;
        v.w = fmaxf(fmaf(v.w, dv, b1[jb + 3]), 0.f) * dv;
        o0[i] = v;
        o1[i] = v;
    }
}

// ---------------- GEMM2 + b2 ----------------
__global__ __launch_bounds__(128) void k_gemm2(const float* __restrict__ y2,
                                               const float* __restrict__ dinv,
                                               const float* __restrict__ W2,
                                               const float* __restrict__ b2,
                                               float* __restrict__ out, int N) {
    __shared__ float w2s[HID * C_OUT];
    __shared__ float b2s[C_OUT];
    int t = threadIdx.x;
    for (int i = t; i < HID * C_OUT; i += 128) w2s[i] = W2[i];
    if (t < C_OUT) b2s[t] = b2[t];
    __syncthreads();
    int i = blockIdx.x * 128 + t;
    if (i >= N) return;
    float dv = dinv[i];
    float a[HID];
#pragma unroll
    for (int k4 = 0; k4 < 4; k4++) {
        float4 v = *(const float4*)&y2[(size_t)i * HID + 4 * k4];
        a[4 * k4 + 0] = v.x * dv; a[4 * k4 + 1] = v.y * dv;
        a[4 * k4 + 2] = v.z * dv; a[4 * k4 + 3] = v.w * dv;
    }
    float o[C_OUT];
#pragma unroll
    for (int j = 0; j < C_OUT; j++) o[j] = b2s[j];
#pragma unroll
    for (int k = 0; k < HID; k++) {
        float av = a[k];
#pragma unroll
        for (int j = 0; j < C_OUT; j++) o[j] += av * w2s[k * C_OUT + j];
    }
#pragma unroll
    for (int jg = 0; jg < C_OUT / 4; jg++) {
        float4 v = make_float4(o[4 * jg + 0], o[4 * jg + 1], o[4 * jg + 2], o[4 * jg + 3]);
        *(float4*)&out[(size_t)i * C_OUT + 4 * jg] = v;
    }
}

// ---------------- launcher ----------------
extern "C" void kernel_launch(void* const* d_in, const int* in_sizes, int n_in,
                              void* d_out, int out_size) {
    const float* x  = (const float*)d_in[0];
    const int*   ei = (const int*)d_in[1];
    const float* W1 = (const float*)d_in[2];
    const float* b1 = (const float*)d_in[3];
    const float* W2 = (const float*)d_in[4];
    const float* b2 = (const float*)d_in[5];
    float* out = (float*)d_out;

    const int N = in_sizes[0] / F_IN;
    const int E = in_sizes[1] / 2;
    const int* src = ei;
    const int* dst = ei + E;

    void *p;
    cudaGetSymbolAddress(&p, g_deg);  int*   deg  = (int*)p;
    cudaGetSymbolAddress(&p, g_dinv); float* dinv = (float*)p;
    cudaGetSymbolAddress(&p, g_B1);   float* B1   = (float*)p;
    cudaGetSymbolAddress(&p, g_B2);   float* B2   = (float*)p;

    const int TB = 256;
    const int nv4 = N * (HID / 4);

    // launch 0-2: zero + degree + dinv
    k_zero_all<<<(nv4 + TB - 1) / TB, TB>>>(deg, (float4*)B1, (float4*)B2, N, nv4);
    k_hist<<<(E + TB - 1) / TB, TB>>>(dst, deg, E);
    k_dinv<<<(N + TB - 1) / TB, TB>>>(deg, dinv, N);
    // launch 3 (profiled): h~ = dinv * (x @ W1) -> red into B1 and B2
    {
        dim3 grid((N + 511) / 512, 2);
        k_gemm1<<<grid, 128>>>(x, W1, dinv, B1, B2, N);
    }
    // launch 4: B2 += A * B1
    {
        int threads = E * 4;
        k_agg<<<(threads + TB - 1) / TB, TB>>>(src, dst, (const float4*)B1, B2, E);
    }
    // launch 5: a~ -> B1 and B2
    k_relubias<<<(nv4 + TB - 1) / TB, TB>>>((const float4*)B2, dinv, b1,
                                            (float4*)B1, (float4*)B2, N);
    // launch 6: B2 += A * B1
    {
        int threads = E * 4;
        k_agg<<<(threads + TB - 1) / TB, TB>>>(src, dst, (const float4*)B1, B2, E);
    }
    // launch 7: out = (dinv * B2) @ W2 + b2
    k_gemm2<<<(N + 127) / 128, 128>>>(B2, dinv, W2, b2, out, N);
}

// round 9
// speedup vs baseline: 1.1018x; 1.0931x over previous
#include <cuda_runtime.h>
#include <cuda_bf16.h>
#include <cstdint>

#define F_IN  512
#define HID   16
#define C_OUT 40
#define MAXN  100000
#define MAXE  3200000

typedef unsigned long long ull;
typedef unsigned int u32;

// ---------------- scratch (static device globals, no allocs) ----------------
__device__ __align__(128) int   g_deg [MAXN];
__device__ __align__(128) float g_dinv[MAXN];
__device__ __align__(128) float g_B1  [MAXN * HID];   // h~, later a~ (agg gather input)
__device__ __align__(128) float g_B2  [MAXN * HID];   // agg accumulators

// ---------------- helpers ----------------
__device__ __forceinline__ void red4(float* p, float a, float b, float c, float d) {
    asm volatile("red.global.add.v4.f32 [%0], {%1,%2,%3,%4};"
                 :: "l"(p), "f"(a), "f"(b), "f"(c), "f"(d) : "memory");
}
__device__ __forceinline__ u32 s2u(const void* p) {
    u32 a;
    asm("{ .reg .u64 t; cvta.to.shared.u64 t, %1; cvt.u32.u64 %0, t; }"
        : "=r"(a) : "l"(p));
    return a;
}
__device__ __forceinline__ void cpa16(u32 dst, const void* src, int sz) {
    asm volatile("cp.async.cg.shared.global [%0], [%1], 16, %2;"
                 :: "r"(dst), "l"(src), "r"(sz) : "memory");
}
__device__ __forceinline__ void cpa_commit() {
    asm volatile("cp.async.commit_group;" ::: "memory");
}
template <int NN>
__device__ __forceinline__ void cpa_wait() {
    asm volatile("cp.async.wait_group %0;" :: "n"(NN) : "memory");
}
__device__ __forceinline__ u32 tf32_of(float f) {
    u32 r;
    asm("cvt.rna.tf32.f32 %0, %1;" : "=r"(r) : "f"(f));
    return r;
}
// split a into hi (tf32) + lo (tf32 of residual)
__device__ __forceinline__ void tf32_split(float a, u32& hi, u32& lo) {
    hi = tf32_of(a);
    lo = tf32_of(a - __uint_as_float(hi));
}
__device__ __forceinline__ void mma_tf32(float& d0, float& d1, float& d2, float& d3,
                                         u32 a0, u32 a1, u32 a2, u32 a3,
                                         u32 b0, u32 b1) {
    asm("mma.sync.aligned.m16n8k8.row.col.f32.tf32.tf32.f32 "
        "{%0,%1,%2,%3}, {%4,%5,%6,%7}, {%8,%9}, {%0,%1,%2,%3};"
        : "+f"(d0), "+f"(d1), "+f"(d2), "+f"(d3)
        : "r"(a0), "r"(a1), "r"(a2), "r"(a3), "r"(b0), "r"(b1));
}

// ---------------- small kernels ----------------
__global__ void k_zero(int* a, int N) {
    int i = blockIdx.x * blockDim.x + threadIdx.x;
    if (i < N) a[i] = 0;
}
__global__ void k_hist(const int* __restrict__ dst, int* deg, int E) {
    int i = blockIdx.x * blockDim.x + threadIdx.x;
    if (i < E) atomicAdd(&deg[dst[i]], 1);
}
__global__ void k_dinv(const int* __restrict__ deg, float* dinv, int N) {
    int i = blockIdx.x * blockDim.x + threadIdx.x;
    if (i < N) dinv[i] = rsqrtf((float)(deg[i] + 1));
}

// ------ GEMM1 v6: tf32 mma (3xTF32 split), cp.async double-buffered ---------
// 256 threads (8 warps x m16 rows = 128 rows/block), n16 = 2 n8 tiles,
// k staged 16 at a time, double-buffered. Full K -> direct dual-store.
#define G1_XS 20   // x row stride (floats): conflict-free A-frag LDS
#define G1_WS 24   // w row stride (floats): conflict-free B-frag LDS
__global__ __launch_bounds__(256) void k_gemm1(const float* __restrict__ x,
                                               const float* __restrict__ W1,
                                               const float* __restrict__ dinv,
                                               float* __restrict__ h0,
                                               float* __restrict__ h1, int N) {
    __shared__ __align__(16) float xs[2][128 * G1_XS];   // 2 x 10KB
    __shared__ __align__(16) float ws[2][16 * G1_WS];    // 2 x 1.5KB
    const int t    = threadIdx.x;
    const int lane = t & 31;
    const int wid  = t >> 5;
    const int gid  = lane >> 2;   // 0..7
    const int tig  = lane & 3;    // 0..3
    const int base = blockIdx.x * 128;

    // x staging: 512 chunks of 16B (128 rows x 4), 2 per thread
    u32 xdst[2][2];
    const float* xsrc[2];
    int xsz[2];
#pragma unroll
    for (int j = 0; j < 2; j++) {
        int idx = t + 256 * j;
        int r = idx >> 2, q = idx & 3;
        xdst[0][j] = s2u(&xs[0][r * G1_XS]) + q * 16;
        xdst[1][j] = s2u(&xs[1][r * G1_XS]) + q * 16;
        xsrc[j] = x + (size_t)(base + r) * F_IN + q * 4;
        xsz[j]  = (base + r < N) ? 16 : 0;
    }
    // w staging: 64 chunks (16 rows x 4), threads t<64
    u32 wdst[2] = {0, 0};
    int wk = 0, wq = 0;
    if (t < 64) {
        wk = t >> 2; wq = t & 3;
        wdst[0] = s2u(&ws[0][wk * G1_WS]) + wq * 16;
        wdst[1] = s2u(&ws[1][wk * G1_WS]) + wq * 16;
    }

    float d0[4] = {0.f, 0.f, 0.f, 0.f};   // n-tile 0 (cols 0-7)
    float d1[4] = {0.f, 0.f, 0.f, 0.f};   // n-tile 1 (cols 8-15)

    // prefetch stage 0
    if (t < 64) cpa16(wdst[0], W1 + (size_t)wk * 16 + wq * 4, 16);
#pragma unroll
    for (int j = 0; j < 2; j++) cpa16(xdst[0][j], xsrc[j], xsz[j]);
    cpa_commit();

    for (int kt = 0; kt < 32; kt++) {
        const int buf = kt & 1;
        if (kt < 31) {
            const int nb = buf ^ 1;
            const int kg = (kt + 1) * 16;
            if (t < 64) cpa16(wdst[nb], W1 + (size_t)(kg + wk) * 16 + wq * 4, 16);
#pragma unroll
            for (int j = 0; j < 2; j++) cpa16(xdst[nb][j], xsrc[j] + kg, xsz[j]);
            cpa_commit();
            cpa_wait<1>();
        } else {
            cpa_wait<0>();
        }
        __syncthreads();

#pragma unroll
        for (int s = 0; s < 2; s++) {
            const int ko = s * 8;
            const int ra = wid * 16 + gid;
            // A fragment (m16k8): conflict-free LDS
            float a0 = xs[buf][ra * G1_XS + ko + tig];
            float a1 = xs[buf][(ra + 8) * G1_XS + ko + tig];
            float a2 = xs[buf][ra * G1_XS + ko + tig + 4];
            float a3 = xs[buf][(ra + 8) * G1_XS + ko + tig + 4];
            // B fragments (k8n8 x 2 tiles)
            float b0 = ws[buf][(ko + tig) * G1_WS + gid];
            float b1 = ws[buf][(ko + tig + 4) * G1_WS + gid];
            float b2 = ws[buf][(ko + tig) * G1_WS + gid + 8];
            float b3 = ws[buf][(ko + tig + 4) * G1_WS + gid + 8];

            u32 a0h, a0l, a1h, a1l, a2h, a2l, a3h, a3l;
            tf32_split(a0, a0h, a0l); tf32_split(a1, a1h, a1l);
            tf32_split(a2, a2h, a2l); tf32_split(a3, a3h, a3l);
            u32 b0h, b0l, b1h, b1l, b2h, b2l, b3h, b3l;
            tf32_split(b0, b0h, b0l); tf32_split(b1, b1h, b1l);
            tf32_split(b2, b2h, b2l); tf32_split(b3, b3h, b3l);

            // 3xTF32: hi*hi + lo*hi + hi*lo   (two independent D chains)
            mma_tf32(d0[0], d0[1], d0[2], d0[3], a0h, a1h, a2h, a3h, b0h, b1h);
            mma_tf32(d1[0], d1[1], d1[2], d1[3], a0h, a1h, a2h, a3h, b2h, b3h);
            mma_tf32(d0[0], d0[1], d0[2], d0[3], a0l, a1l, a2l, a3l, b0h, b1h);
            mma_tf32(d1[0], d1[1], d1[2], d1[3], a0l, a1l, a2l, a3l, b2h, b3h);
            mma_tf32(d0[0], d0[1], d0[2], d0[3], a0h, a1h, a2h, a3h, b0l, b1l);
            mma_tf32(d1[0], d1[1], d1[2], d1[3], a0h, a1h, a2h, a3h, b2l, b3l);
        }
        __syncthreads();
    }

    // epilogue: scale by dinv, dual-store (B1 gather input + B2 self-loop init)
    {
        int r0 = base + wid * 16 + gid;
        int r1 = r0 + 8;
        if (r0 < N) {
            float dv = dinv[r0];
            float2 v0 = make_float2(d0[0] * dv, d0[1] * dv);
            float2 v1 = make_float2(d1[0] * dv, d1[1] * dv);
            *(float2*)&h0[(size_t)r0 * HID + 2 * tig]     = v0;
            *(float2*)&h0[(size_t)r0 * HID + 8 + 2 * tig] = v1;
            *(float2*)&h1[(size_t)r0 * HID + 2 * tig]     = v0;
            *(float2*)&h1[(size_t)r0 * HID + 8 + 2 * tig] = v1;
        }
        if (r1 < N) {
            float dv = dinv[r1];
            float2 v0 = make_float2(d0[2] * dv, d0[3] * dv);
            float2 v1 = make_float2(d1[2] * dv, d1[3] * dv);
            *(float2*)&h0[(size_t)r1 * HID + 2 * tig]     = v0;
            *(float2*)&h0[(size_t)r1 * HID + 8 + 2 * tig] = v1;
            *(float2*)&h1[(size_t)r1 * HID + 2 * tig]     = v0;
            *(float2*)&h1[(size_t)r1 * HID + 8 + 2 * tig] = v1;
        }
    }
}

// ---------------- edge aggregation: out[dst] += in[src], 4 thr/edge ----------
__global__ void k_agg(const int* __restrict__ src, const int* __restrict__ dst,
                      const float4* __restrict__ in4, float* out, int E) {
    int tid = blockIdx.x * blockDim.x + threadIdx.x;
    int e = tid >> 2;
    int c = tid & 3;
    if (e < E) {
        int s = src[e];
        int d = dst[e];
        float4 v = __ldg(&in4[(size_t)s * 4 + c]);
        red4(&out[((size_t)d * 4 + c) * 4], v.x, v.y, v.z, v.w);
    }
}

// ---------------- a~ = dinv * relu(dinv * y1 + b1), dual store --------------
__global__ void k_relubias(const float4* __restrict__ in4, const float* __restrict__ dinv,
                           const float* __restrict__ b1,
                           float4* __restrict__ o0, float4* __restrict__ o1, int N) {
    int i = blockIdx.x * blockDim.x + threadIdx.x;
    if (i < N * (HID / 4)) {
        float dv = dinv[i >> 2];
        int jb = (i & 3) * 4;
        float4 v = in4[i];
        v.x = fmaxf(fmaf(v.x, dv, b1[jb + 0]), 0.f) * dv;
        v.y = fmaxf(fmaf(v.y, dv, b1[jb + 1]), 0.f) * dv;
        v.z = fmaxf(fmaf(v.z, dv, b1[jb + 2]), 0.f) * dv;
        v.w = fmaxf(fmaf(v.w, dv, b1[jb + 3]), 0.f) * dv;
        o0[i] = v;
        o1[i] = v;
    }
}

// ---------------- GEMM2 + b2 ----------------
__global__ __launch_bounds__(128) void k_gemm2(const float* __restrict__ y2,
                                               const float* __restrict__ dinv,
                                               const float* __restrict__ W2,
                                               const float* __restrict__ b2,
                                               float* __restrict__ out, int N) {
    __shared__ float w2s[HID * C_OUT];
    __shared__ float b2s[C_OUT];
    int t = threadIdx.x;
    for (int i = t; i < HID * C_OUT; i += 128) w2s[i] = W2[i];
    if (t < C_OUT) b2s[t] = b2[t];
    __syncthreads();
    int i = blockIdx.x * 128 + t;
    if (i >= N) return;
    float dv = dinv[i];
    float a[HID];
#pragma unroll
    for (int k4 = 0; k4 < 4; k4++) {
        float4 v = *(const float4*)&y2[(size_t)i * HID + 4 * k4];
        a[4 * k4 + 0] = v.x * dv; a[4 * k4 + 1] = v.y * dv;
        a[4 * k4 + 2] = v.z * dv; a[4 * k4 + 3] = v.w * dv;
    }
    float o[C_OUT];
#pragma unroll
    for (int j = 0; j < C_OUT; j++) o[j] = b2s[j];
#pragma unroll
    for (int k = 0; k < HID; k++) {
        float av = a[k];
#pragma unroll
        for (int j = 0; j < C_OUT; j++) o[j] += av * w2s[k * C_OUT + j];
    }
#pragma unroll
    for (int jg = 0; jg < C_OUT / 4; jg++) {
        float4 v = make_float4(o[4 * jg + 0], o[4 * jg + 1], o[4 * jg + 2], o[4 * jg + 3]);
        *(float4*)&out[(size_t)i * C_OUT + 4 * jg] = v;
    }
}

// ---------------- launcher ----------------
extern "C" void kernel_launch(void* const* d_in, const int* in_sizes, int n_in,
                              void* d_out, int out_size) {
    const float* x  = (const float*)d_in[0];
    const int*   ei = (const int*)d_in[1];
    const float* W1 = (const float*)d_in[2];
    const float* b1 = (const float*)d_in[3];
    const float* W2 = (const float*)d_in[4];
    const float* b2 = (const float*)d_in[5];
    float* out = (float*)d_out;

    const int N = in_sizes[0] / F_IN;
    const int E = in_sizes[1] / 2;
    const int* src = ei;
    const int* dst = ei + E;

    void *p;
    cudaGetSymbolAddress(&p, g_deg);  int*   deg  = (int*)p;
    cudaGetSymbolAddress(&p, g_dinv); float* dinv = (float*)p;
    cudaGetSymbolAddress(&p, g_B1);   float* B1   = (float*)p;
    cudaGetSymbolAddress(&p, g_B2);   float* B2   = (float*)p;

    const int TB = 256;
    const int nv4 = N * (HID / 4);

    // launch 0-2: degree + dinv
    k_zero<<<(N + TB - 1) / TB, TB>>>(deg, N);
    k_hist<<<(E + TB - 1) / TB, TB>>>(dst, deg, E);
    k_dinv<<<(N + TB - 1) / TB, TB>>>(deg, dinv, N);
    // launch 3 (profiled): h~ = dinv * (x @ W1) -> B1 and B2 (self-loop init)
    k_gemm1<<<(N + 127) / 128, 256>>>(x, W1, dinv, B1, B2, N);
    // launch 4: B2 += A * B1
    {
        int threads = E * 4;
        k_agg<<<(threads + TB - 1) / TB, TB>>>(src, dst, (const float4*)B1, B2, E);
    }
    // launch 5: a~ -> B1 and B2
    k_relubias<<<(nv4 + TB - 1) / TB, TB>>>((const float4*)B2, dinv, b1,
                                            (float4*)B1, (float4*)B2, N);
    // launch 6: B2 += A * B1
    {
        int threads = E * 4;
        k_agg<<<(threads + TB - 1) / TB, TB>>>(src, dst, (const float4*)B1, B2, E);
    }
    // launch 7: out = (dinv * B2) @ W2 + b2
    k_gemm2<<<(N + 127) / 128, 128>>>(B2, dinv, W2, b2, out, N);
}

// round 10
// speedup vs baseline: 1.1137x; 1.0108x over previous
#include <cuda_runtime.h>
#include <cuda_bf16.h>
#include <cstdint>

#define F_IN  512
#define HID   16
#define C_OUT 40
#define MAXN  100000
#define MAXE  3200000

typedef unsigned long long ull;
typedef unsigned int u32;

// ---------------- scratch (static device globals, no allocs) ----------------
__device__ __align__(128) int   g_deg [MAXN];
__device__ __align__(128) float g_dinv[MAXN];
__device__ __align__(128) float g_B1  [MAXN * HID];   // h~, later a~ (agg gather input)
__device__ __align__(128) float g_B2  [MAXN * HID];   // agg accumulators
__device__ __align__(128) float g_W1h [F_IN * HID];   // tf32 hi part of W1
__device__ __align__(128) float g_W1l [F_IN * HID];   // tf32 lo part of W1

// ---------------- helpers ----------------
__device__ __forceinline__ void red4(float* p, float a, float b, float c, float d) {
    asm volatile("red.global.add.v4.f32 [%0], {%1,%2,%3,%4};"
                 :: "l"(p), "f"(a), "f"(b), "f"(c), "f"(d) : "memory");
}
__device__ __forceinline__ u32 s2u(const void* p) {
    u32 a;
    asm("{ .reg .u64 t; cvta.to.shared.u64 t, %1; cvt.u32.u64 %0, t; }"
        : "=r"(a) : "l"(p));
    return a;
}
__device__ __forceinline__ void cpa16(u32 dst, const void* src, int sz) {
    asm volatile("cp.async.cg.shared.global [%0], [%1], 16, %2;"
                 :: "r"(dst), "l"(src), "r"(sz) : "memory");
}
__device__ __forceinline__ void cpa_commit() {
    asm volatile("cp.async.commit_group;" ::: "memory");
}
template <int NN>
__device__ __forceinline__ void cpa_wait() {
    asm volatile("cp.async.wait_group %0;" :: "n"(NN) : "memory");
}
__device__ __forceinline__ u32 tf32_of(float f) {
    u32 r;
    asm("cvt.rna.tf32.f32 %0, %1;" : "=r"(r) : "f"(f));
    return r;
}
__device__ __forceinline__ void tf32_split(float a, u32& hi, u32& lo) {
    hi = tf32_of(a);
    lo = tf32_of(a - __uint_as_float(hi));
}
__device__ __forceinline__ void mma_tf32(float& d0, float& d1, float& d2, float& d3,
                                         u32 a0, u32 a1, u32 a2, u32 a3,
                                         u32 b0, u32 b1) {
    asm("mma.sync.aligned.m16n8k8.row.col.f32.tf32.tf32.f32 "
        "{%0,%1,%2,%3}, {%4,%5,%6,%7}, {%8,%9}, {%0,%1,%2,%3};"
        : "+f"(d0), "+f"(d1), "+f"(d2), "+f"(d3)
        : "r"(a0), "r"(a1), "r"(a2), "r"(a3), "r"(b0), "r"(b1));
}

// ---------------- small kernels ----------------
__global__ void k_zero(int* a, int N) {
    int i = blockIdx.x * blockDim.x + threadIdx.x;
    if (i < N) a[i] = 0;
}
__global__ void k_hist(const int* __restrict__ dst, int* deg, int E) {
    int i = blockIdx.x * blockDim.x + threadIdx.x;
    if (i < E) atomicAdd(&deg[dst[i]], 1);
}
__global__ void k_dinv(const int* __restrict__ deg, float* dinv, int N) {
    int i = blockIdx.x * blockDim.x + threadIdx.x;
    if (i < N) dinv[i] = rsqrtf((float)(deg[i] + 1));
}
// W1 tf32 hi/lo precompute
__global__ void k_wsplit(const float* __restrict__ W1, float* wh, float* wl, int n) {
    int i = blockIdx.x * blockDim.x + threadIdx.x;
    if (i < n) {
        float w = W1[i];
        u32 h, l;
        tf32_split(w, h, l);
        wh[i] = __uint_as_float(h);
        wl[i] = __uint_as_float(l);
    }
}

// ------ GEMM1 v7: tf32 mma, precomputed W split, 32-k stages ----------------
// 256 threads (8 warps x m16 = 128 rows/block), n16 = 2 n8 tiles.
#define G1_XS 36   // x row stride (floats): conflict-free A-frag banks
#define G1_WS 24   // w row stride (floats): conflict-free B-frag banks
__global__ __launch_bounds__(256) void k_gemm1(const float* __restrict__ x,
                                               const float* __restrict__ W1h,
                                               const float* __restrict__ W1l,
                                               const float* __restrict__ dinv,
                                               float* __restrict__ h0,
                                               float* __restrict__ h1, int N) {
    __shared__ __align__(16) float xs[2][128 * G1_XS];   // 2 x 18KB
    __shared__ __align__(16) float wh[2][32 * G1_WS];    // 2 x 3KB
    __shared__ __align__(16) float wl[2][32 * G1_WS];    // 2 x 3KB
    const int t    = threadIdx.x;
    const int lane = t & 31;
    const int wid  = t >> 5;
    const int gid  = lane >> 2;   // 0..7
    const int tig  = lane & 3;    // 0..3
    const int base = blockIdx.x * 128;

    // x staging: 1024 chunks of 16B (128 rows x 8), 4 per thread
    u32 xdst[2][4];
    const float* xsrc[4];
    int xsz[4];
#pragma unroll
    for (int j = 0; j < 4; j++) {
        int idx = t + 256 * j;
        int r = idx >> 3, q = idx & 7;
        xdst[0][j] = s2u(&xs[0][r * G1_XS]) + q * 16;
        xdst[1][j] = s2u(&xs[1][r * G1_XS]) + q * 16;
        xsrc[j] = x + (size_t)(base + r) * F_IN + q * 4;
        xsz[j]  = (base + r < N) ? 16 : 0;
    }
    // w staging: hi 128 chunks (t<128), lo 128 chunks (t in [128,256))
    const int wk = (t & 127) >> 2, wq = t & 3;
    u32 wdst[2];
    const float* wsrcb;
    if (t < 128) {
        wdst[0] = s2u(&wh[0][wk * G1_WS]) + wq * 16;
        wdst[1] = s2u(&wh[1][wk * G1_WS]) + wq * 16;
        wsrcb = W1h + (size_t)wk * 16 + wq * 4;
    } else {
        wdst[0] = s2u(&wl[0][wk * G1_WS]) + wq * 16;
        wdst[1] = s2u(&wl[1][wk * G1_WS]) + wq * 16;
        wsrcb = W1l + (size_t)wk * 16 + wq * 4;
    }

    float d0[4] = {0.f, 0.f, 0.f, 0.f};
    float d1[4] = {0.f, 0.f, 0.f, 0.f};

    // prefetch stage 0
    cpa16(wdst[0], wsrcb, 16);
#pragma unroll
    for (int j = 0; j < 4; j++) cpa16(xdst[0][j], xsrc[j], xsz[j]);
    cpa_commit();

    for (int kt = 0; kt < 16; kt++) {
        const int buf = kt & 1;
        if (kt < 15) {
            const int nb = buf ^ 1;
            const int kg = (kt + 1) * 32;
            cpa16(wdst[nb], wsrcb + (size_t)kg * 16, 16);
#pragma unroll
            for (int j = 0; j < 4; j++) cpa16(xdst[nb][j], xsrc[j] + kg, xsz[j]);
            cpa_commit();
            cpa_wait<1>();
        } else {
            cpa_wait<0>();
        }
        __syncthreads();

        const int ra = wid * 16 + gid;
#pragma unroll
        for (int s = 0; s < 4; s++) {
            const int ko = s * 8;
            // A fragment (m16k8), conflict-free
            float a0 = xs[buf][ra * G1_XS + ko + tig];
            float a1 = xs[buf][(ra + 8) * G1_XS + ko + tig];
            float a2 = xs[buf][ra * G1_XS + ko + tig + 4];
            float a3 = xs[buf][(ra + 8) * G1_XS + ko + tig + 4];
            u32 a0h, a0l, a1h, a1l, a2h, a2l, a3h, a3l;
            tf32_split(a0, a0h, a0l); tf32_split(a1, a1h, a1l);
            tf32_split(a2, a2h, a2l); tf32_split(a3, a3h, a3l);
            // B fragments hi+lo, conflict-free
            u32 b0h = __float_as_uint(wh[buf][(ko + tig) * G1_WS + gid]);
            u32 b1h = __float_as_uint(wh[buf][(ko + tig + 4) * G1_WS + gid]);
            u32 b2h = __float_as_uint(wh[buf][(ko + tig) * G1_WS + gid + 8]);
            u32 b3h = __float_as_uint(wh[buf][(ko + tig + 4) * G1_WS + gid + 8]);
            u32 b0l = __float_as_uint(wl[buf][(ko + tig) * G1_WS + gid]);
            u32 b1l = __float_as_uint(wl[buf][(ko + tig + 4) * G1_WS + gid]);
            u32 b2l = __float_as_uint(wl[buf][(ko + tig) * G1_WS + gid + 8]);
            u32 b3l = __float_as_uint(wl[buf][(ko + tig + 4) * G1_WS + gid + 8]);

            // 3xTF32: hi*hi + lo*hi + hi*lo
            mma_tf32(d0[0], d0[1], d0[2], d0[3], a0h, a1h, a2h, a3h, b0h, b1h);
            mma_tf32(d1[0], d1[1], d1[2], d1[3], a0h, a1h, a2h, a3h, b2h, b3h);
            mma_tf32(d0[0], d0[1], d0[2], d0[3], a0l, a1l, a2l, a3l, b0h, b1h);
            mma_tf32(d1[0], d1[1], d1[2], d1[3], a0l, a1l, a2l, a3l, b2h, b3h);
            mma_tf32(d0[0], d0[1], d0[2], d0[3], a0h, a1h, a2h, a3h, b0l, b1l);
            mma_tf32(d1[0], d1[1], d1[2], d1[3], a0h, a1h, a2h, a3h, b2l, b3l);
        }
        __syncthreads();
    }

    // epilogue: scale by dinv, dual-store (B1 gather input + B2 self-loop init)
    {
        int r0 = base + wid * 16 + gid;
        int r1 = r0 + 8;
        if (r0 < N) {
            float dv = dinv[r0];
            float2 v0 = make_float2(d0[0] * dv, d0[1] * dv);
            float2 v1 = make_float2(d1[0] * dv, d1[1] * dv);
            *(float2*)&h0[(size_t)r0 * HID + 2 * tig]     = v0;
            *(float2*)&h0[(size_t)r0 * HID + 8 + 2 * tig] = v1;
            *(float2*)&h1[(size_t)r0 * HID + 2 * tig]     = v0;
            *(float2*)&h1[(size_t)r0 * HID + 8 + 2 * tig] = v1;
        }
        if (r1 < N) {
            float dv = dinv[r1];
            float2 v0 = make_float2(d0[2] * dv, d0[3] * dv);
            float2 v1 = make_float2(d1[2] * dv, d1[3] * dv);
            *(float2*)&h0[(size_t)r1 * HID + 2 * tig]     = v0;
            *(float2*)&h0[(size_t)r1 * HID + 8 + 2 * tig] = v1;
            *(float2*)&h1[(size_t)r1 * HID + 2 * tig]     = v0;
            *(float2*)&h1[(size_t)r1 * HID + 8 + 2 * tig] = v1;
        }
    }
}

// ---------------- edge aggregation: out[dst] += in[src], 4 thr/edge ----------
__global__ void k_agg(const int* __restrict__ src, const int* __restrict__ dst,
                      const float4* __restrict__ in4, float* out, int E) {
    int tid = blockIdx.x * blockDim.x + threadIdx.x;
    int e = tid >> 2;
    int c = tid & 3;
    if (e < E) {
        int s = src[e];
        int d = dst[e];
        float4 v = __ldg(&in4[(size_t)s * 4 + c]);
        red4(&out[((size_t)d * 4 + c) * 4], v.x, v.y, v.z, v.w);
    }
}

// ---------------- a~ = dinv * relu(dinv * y1 + b1), dual store --------------
__global__ void k_relubias(const float4* __restrict__ in4, const float* __restrict__ dinv,
                           const float* __restrict__ b1,
                           float4* __restrict__ o0, float4* __restrict__ o1, int N) {
    int i = blockIdx.x * blockDim.x + threadIdx.x;
    if (i < N * (HID / 4)) {
        float dv = dinv[i >> 2];
        int jb = (i & 3) * 4;
        float4 v = in4[i];
        v.x = fmaxf(fmaf(v.x, dv, b1[jb + 0]), 0.f) * dv;
        v.y = fmaxf(fmaf(v.y, dv, b1[jb + 1]), 0.f) * dv;
        v.z = fmaxf(fmaf(v.z, dv, b1[jb + 2]), 0.f) * dv;
        v.w = fmaxf(fmaf(v.w, dv, b1[jb + 3]), 0.f) * dv;
        o0[i] = v;
        o1[i] = v;
    }
}

// ---------------- GEMM2 + b2 ----------------
__global__ __launch_bounds__(128) void k_gemm2(const float* __restrict__ y2,
                                               const float* __restrict__ dinv,
                                               const float* __restrict__ W2,
                                               const float* __restrict__ b2,
                                               float* __restrict__ out, int N) {
    __shared__ float w2s[HID * C_OUT];
    __shared__ float b2s[C_OUT];
    int t = threadIdx.x;
    for (int i = t; i < HID * C_OUT; i += 128) w2s[i] = W2[i];
    if (t < C_OUT) b2s[t] = b2[t];
    __syncthreads();
    int i = blockIdx.x * 128 + t;
    if (i >= N) return;
    float dv = dinv[i];
    float a[HID];
#pragma unroll
    for (int k4 = 0; k4 < 4; k4++) {
        float4 v = *(const float4*)&y2[(size_t)i * HID + 4 * k4];
        a[4 * k4 + 0] = v.x * dv; a[4 * k4 + 1] = v.y * dv;
        a[4 * k4 + 2] = v.z * dv; a[4 * k4 + 3] = v.w * dv;
    }
    float o[C_OUT];
#pragma unroll
    for (int j = 0; j < C_OUT; j++) o[j] = b2s[j];
#pragma unroll
    for (int k = 0; k < HID; k++) {
        float av = a[k];
#pragma unroll
        for (int j = 0; j < C_OUT; j++) o[j] += av * w2s[k * C_OUT + j];
    }
#pragma unroll
    for (int jg = 0; jg < C_OUT / 4; jg++) {
        float4 v = make_float4(o[4 * jg + 0], o[4 * jg + 1], o[4 * jg + 2], o[4 * jg + 3]);
        *(float4*)&out[(size_t)i * C_OUT + 4 * jg] = v;
    }
}

// ---------------- launcher ----------------
extern "C" void kernel_launch(void* const* d_in, const int* in_sizes, int n_in,
                              void* d_out, int out_size) {
    const float* x  = (const float*)d_in[0];
    const int*   ei = (const int*)d_in[1];
    const float* W1 = (const float*)d_in[2];
    const float* b1 = (const float*)d_in[3];
    const float* W2 = (const float*)d_in[4];
    const float* b2 = (const float*)d_in[5];
    float* out = (float*)d_out;

    const int N = in_sizes[0] / F_IN;
    const int E = in_sizes[1] / 2;
    const int* src = ei;
    const int* dst = ei + E;

    void *p;
    cudaGetSymbolAddress(&p, g_deg);  int*   deg  = (int*)p;
    cudaGetSymbolAddress(&p, g_dinv); float* dinv = (float*)p;
    cudaGetSymbolAddress(&p, g_B1);   float* B1   = (float*)p;
    cudaGetSymbolAddress(&p, g_B2);   float* B2   = (float*)p;
    cudaGetSymbolAddress(&p, g_W1h);  float* W1h  = (float*)p;
    cudaGetSymbolAddress(&p, g_W1l);  float* W1l  = (float*)p;

    const int TB = 256;
    const int nv4 = N * (HID / 4);

    // launch 0-3: degree + dinv + W split
    k_zero<<<(N + TB - 1) / TB, TB>>>(deg, N);
    k_hist<<<(E + TB - 1) / TB, TB>>>(dst, deg, E);
    k_dinv<<<(N + TB - 1) / TB, TB>>>(deg, dinv, N);
    k_wsplit<<<(F_IN * HID + TB - 1) / TB, TB>>>(W1, W1h, W1l, F_IN * HID);
    // launch 4: h~ = dinv * (x @ W1) -> B1 and B2 (self-loop init)
    k_gemm1<<<(N + 127) / 128, 256>>>(x, W1h, W1l, dinv, B1, B2, N);
    // launch 5: B2 += A * B1
    {
        int threads = E * 4;
        k_agg<<<(threads + TB - 1) / TB, TB>>>(src, dst, (const float4*)B1, B2, E);
    }
    // launch 6: a~ -> B1 and B2
    k_relubias<<<(nv4 + TB - 1) / TB, TB>>>((const float4*)B2, dinv, b1,
                                            (float4*)B1, (float4*)B2, N);
    // launch 7: B2 += A * B1
    {
        int threads = E * 4;
        k_agg<<<(threads + TB - 1) / TB, TB>>>(src, dst, (const float4*)B1, B2, E);
    }
    // launch 8: out = (dinv * B2) @ W2 + b2
    k_gemm2<<<(N + 127) / 128, 128>>>(B2, dinv, W2, b2, out, N);
}